// round 9
// baseline (speedup 1.0000x reference)
#include <cuda_runtime.h>
#include <cuda_fp16.h>

#define T_TOK 500000
#define M_MEN 50000
#define B_BAG 5000
#define V_VOC 100000
#define D_DIM 256
#define K_TYP 100
#define K_PAD 128
#define ATT_CAP 2048

// Scratch (no allocations allowed)
__device__ __half g_emb_h[V_VOC * D_DIM];       // 51.2 MB fp16 embedding table
__device__ __half g_men_emb[M_MEN * D_DIM];     // 25.6 MB fp16 intermediate
__device__ float  g_sel_part[2 * M_MEN];        // per-half partial dots (fp32)
__device__ float  g_bag_emb[B_BAG * D_DIM];     // 5.12 MB
__device__ float  g_Wt[D_DIM * K_PAD];          // 128 KB, W transposed d-major
__device__ int    g_men_type[M_MEN];            // per-mention selected type

#define K0_ARG_BLOCKS ((B_BAG + 7) / 8)
#define K0_TR_BLOCKS  ((D_DIM * K_PAD + 255) / 256)

// ---------------------------------------------------------------------------
// KC: convert word_embedding fp32 -> fp16 table (streaming read, resident write)
// ---------------------------------------------------------------------------
__global__ void kc_conv(const float* __restrict__ emb, __half* __restrict__ emb_h) {
    int idx = blockIdx.x * blockDim.x + threadIdx.x;    // float4 index
    const int N4 = V_VOC * D_DIM / 4;                   // 6.4M
    if (idx >= N4) return;
    float4 v = __ldcs(&((const float4*)emb)[idx]);      // don't cache fp32 copy
    __half2 h01 = __floats2half2_rn(v.x, v.y);
    __half2 h23 = __floats2half2_rn(v.z, v.w);
    uint2 packed;
    packed.x = *(const unsigned int*)&h01;
    packed.y = *(const unsigned int*)&h23;
    ((uint2*)emb_h)[idx] = packed;                      // keep fp16 table in L2
}

// ---------------------------------------------------------------------------
// K0 (merged): blocks [0, K0_ARG_BLOCKS) do per-bag argmax + mention scatter;
//              blocks [K0_ARG_BLOCKS, +K0_TR_BLOCKS) transpose W -> Wt.
// ---------------------------------------------------------------------------
__global__ void k0_prep(const float* __restrict__ typeT,
                        const int*   __restrict__ scope,
                        const float* __restrict__ W,
                        int*   __restrict__ men_type,
                        float* __restrict__ Wt) {
    if (blockIdx.x >= K0_ARG_BLOCKS) {
        int idx = (blockIdx.x - K0_ARG_BLOCKS) * blockDim.x + threadIdx.x;
        if (idx < D_DIM * K_PAD) {
            int d = idx >> 7, k = idx & 127;
            Wt[idx] = (k < K_TYP) ? W[(size_t)k * D_DIM + d] : 0.f;
        }
        return;
    }
    int b    = blockIdx.x * (blockDim.x >> 5) + (threadIdx.x >> 5);
    int lane = threadIdx.x & 31;
    if (b >= B_BAG) return;
    float best = -INFINITY; int bi = K_TYP;
    for (int k = lane; k < K_TYP; k += 32) {
        float v = typeT[(size_t)b * K_TYP + k];
        if (v > best) { best = v; bi = k; }
    }
    #pragma unroll
    for (int off = 16; off; off >>= 1) {
        float ov = __shfl_xor_sync(0xffffffffu, best, off);
        int   oi = __shfl_xor_sync(0xffffffffu, bi,   off);
        if (ov > best || (ov == best && oi < bi)) { best = ov; bi = oi; }
    }
    int s = scope[b], e = scope[b + 1];
    for (int j = s + lane; j < e; j += 32) men_type[j] = bi;
}

// ---------------------------------------------------------------------------
// K1: TWO warps per mention (each owns 128 dims = 1 uint2 / 4 halves per lane).
//     Gathers from fp16 table (L2-resident), 4-token unroll, fp32 accumulate.
//     men_emb stored fp16 with PLAIN store (keep L2-resident for k3a).
// ---------------------------------------------------------------------------
__global__ void k1_mention(const int*   __restrict__ feat,
                           const int*   __restrict__ offs,
                           const float* __restrict__ lw,
                           const int*   __restrict__ men_type) {
    int wid  = threadIdx.x >> 5;               // 0..7
    int lane = threadIdx.x & 31;
    int gw   = blockIdx.x * 8 + wid;
    int m    = gw >> 1;
    int half = gw & 1;

    int start = offs[m];
    int end   = (m + 1 < M_MEN) ? offs[m + 1] : T_TOK;

    int col4 = half * 32 + lane;               // 4-dim group index (0..63)
    const uint2* eh = (const uint2*)g_emb_h;   // row = 64 uint2

    float4 acc = make_float4(0.f, 0.f, 0.f, 0.f);
    int p = start;
    for (; p + 4 <= end; p += 4) {
        int t0 = feat[p],     t1 = feat[p + 1];
        int t2 = feat[p + 2], t3 = feat[p + 3];
        uint2 u0 = eh[(size_t)t0 * 64 + col4];
        uint2 u1 = eh[(size_t)t1 * 64 + col4];
        uint2 u2 = eh[(size_t)t2 * 64 + col4];
        uint2 u3 = eh[(size_t)t3 * 64 + col4];
        float2 a0 = __half22float2(*(const __half2*)&u0.x);
        float2 b0 = __half22float2(*(const __half2*)&u0.y);
        float2 a1 = __half22float2(*(const __half2*)&u1.x);
        float2 b1 = __half22float2(*(const __half2*)&u1.y);
        float2 a2 = __half22float2(*(const __half2*)&u2.x);
        float2 b2 = __half22float2(*(const __half2*)&u2.y);
        float2 a3 = __half22float2(*(const __half2*)&u3.x);
        float2 b3 = __half22float2(*(const __half2*)&u3.y);
        acc.x += (a0.x + a1.x) + (a2.x + a3.x);
        acc.y += (a0.y + a1.y) + (a2.y + a3.y);
        acc.z += (b0.x + b1.x) + (b2.x + b3.x);
        acc.w += (b0.y + b1.y) + (b2.y + b3.y);
    }
    for (; p < end; p++) {
        int t0 = feat[p];
        uint2 u0 = eh[(size_t)t0 * 64 + col4];
        float2 a0 = __half22float2(*(const __half2*)&u0.x);
        float2 b0 = __half22float2(*(const __half2*)&u0.y);
        acc.x += a0.x; acc.y += a0.y; acc.z += b0.x; acc.w += b0.y;
    }
    float inv = 1.0f / (float)(end - start);
    acc.x *= inv; acc.y *= inv; acc.z *= inv; acc.w *= inv;

    // fp16 pack, PLAIN store (stay L2-resident; read by k3a)
    __half2 h01 = __floats2half2_rn(acc.x, acc.y);
    __half2 h23 = __floats2half2_rn(acc.z, acc.w);
    uint2 packed;
    packed.x = *(const unsigned int*)&h01;
    packed.y = *(const unsigned int*)&h23;
    ((uint2*)g_men_emb)[(size_t)m * 64 + col4] = packed;

    int t = men_type[m];
    float4 w = ((const float4*)(lw + (size_t)t * D_DIM))[col4];
    float d = acc.x * w.x + acc.y * w.y + acc.z * w.z + acc.w * w.w;
    #pragma unroll
    for (int off = 16; off; off >>= 1) d += __shfl_xor_sync(0xffffffffu, d, off);
    if (lane == 0) g_sel_part[gw] = d;
}

// ---------------------------------------------------------------------------
// K3a: one 128-thread block per bag. Prologue: warp-0 softmax stats + smem
//      att cache (all threads fill). Main loop: no syncs, 2 loads in flight.
// ---------------------------------------------------------------------------
__global__ void k3a_bagemb(const int* __restrict__ scope,
                           float*     __restrict__ bag_emb) {
    int b   = blockIdx.x;
    int tid = threadIdx.x;       // 128
    int q   = tid >> 6;          // 0..1 mention phase
    int c   = tid & 63;          // uint2 (4-half) column group
    int lane = tid & 31, warp = tid >> 5;
    int s = scope[b], e = scope[b + 1];
    int n = e - s;

    __shared__ float s_mx, s_inv;
    __shared__ float s_att[ATT_CAP];

    if (warp == 0) {
        float mx = -INFINITY;
        for (int m = s + lane; m < e; m += 32)
            mx = fmaxf(mx, g_sel_part[2 * m] + g_sel_part[2 * m + 1]);
        #pragma unroll
        for (int off = 16; off; off >>= 1)
            mx = fmaxf(mx, __shfl_xor_sync(0xffffffffu, mx, off));
        float sum = 0.f;
        for (int m = s + lane; m < e; m += 32)
            sum += expf(g_sel_part[2 * m] + g_sel_part[2 * m + 1] - mx);
        #pragma unroll
        for (int off = 16; off; off >>= 1)
            sum += __shfl_xor_sync(0xffffffffu, sum, off);
        if (lane == 0) { s_mx = mx; s_inv = 1.0f / sum; }
    }
    __syncthreads();
    float mx = s_mx, inv = s_inv;
    int ncap = (n < ATT_CAP) ? n : ATT_CAP;
    for (int i = tid; i < ncap; i += 128)
        s_att[i] = expf(g_sel_part[2 * (s + i)] + g_sel_part[2 * (s + i) + 1] - mx) * inv;
    __syncthreads();

    const uint2* me = (const uint2*)g_men_emb;
    float4 acc = make_float4(0.f, 0.f, 0.f, 0.f);

    if (n <= ATT_CAP) {                         // fast path (always in practice)
        int m = s + q;
        for (; m + 2 < e; m += 4) {
            float w0 = s_att[m - s];
            float w1 = s_att[m + 2 - s];
            uint2 u0 = __ldcg(&me[(size_t)m       * 64 + c]);
            uint2 u1 = __ldcg(&me[(size_t)(m + 2) * 64 + c]);
            float2 a01 = __half22float2(*(const __half2*)&u0.x);
            float2 a23 = __half22float2(*(const __half2*)&u0.y);
            float2 b01 = __half22float2(*(const __half2*)&u1.x);
            float2 b23 = __half22float2(*(const __half2*)&u1.y);
            acc.x += w0 * a01.x + w1 * b01.x;
            acc.y += w0 * a01.y + w1 * b01.y;
            acc.z += w0 * a23.x + w1 * b23.x;
            acc.w += w0 * a23.y + w1 * b23.y;
        }
        if (m < e) {
            float w0 = s_att[m - s];
            uint2 u0 = __ldcg(&me[(size_t)m * 64 + c]);
            float2 a01 = __half22float2(*(const __half2*)&u0.x);
            float2 a23 = __half22float2(*(const __half2*)&u0.y);
            acc.x += w0 * a01.x; acc.y += w0 * a01.y;
            acc.z += w0 * a23.x; acc.w += w0 * a23.y;
        }
    } else {                                     // safe fallback for huge bags
        for (int m = s + q; m < e; m += 2) {
            float w0 = expf(g_sel_part[2 * m] + g_sel_part[2 * m + 1] - mx) * inv;
            uint2 u0 = __ldcg(&me[(size_t)m * 64 + c]);
            float2 a01 = __half22float2(*(const __half2*)&u0.x);
            float2 a23 = __half22float2(*(const __half2*)&u0.y);
            acc.x += w0 * a01.x; acc.y += w0 * a01.y;
            acc.z += w0 * a23.x; acc.w += w0 * a23.y;
        }
    }

    __shared__ float4 red[2][64];
    red[q][c] = acc;
    __syncthreads();
    if (tid < 64) {
        float4 r0 = red[0][tid], r1 = red[1][tid];
        float4 r;
        r.x = r0.x + r1.x; r.y = r0.y + r1.y;
        r.z = r0.z + r1.z; r.w = r0.w + r1.w;
        ((float4*)(bag_emb + (size_t)b * D_DIM))[tid] = r;
    }
}

// ---------------------------------------------------------------------------
// K3b: GEMM out[5000,100] = bag_emb @ W^T using d-major g_Wt.
// ---------------------------------------------------------------------------
#define GEMM_BM 16
#define DSTAGE  64
__global__ void k3b_gemm(const float* __restrict__ A,
                         const float* __restrict__ Wt,
                         float*       __restrict__ out) {
    __shared__ float sW[DSTAGE][K_PAD];
    __shared__ float sA[DSTAGE][GEMM_BM + 4];
    int tid = threadIdx.x;                    // 128 threads
    int kt = tid & 31;
    int bt = tid >> 5;
    int bag0 = blockIdx.x * GEMM_BM;

    float4 acc[4];
    #pragma unroll
    for (int r = 0; r < 4; r++) acc[r] = make_float4(0.f, 0.f, 0.f, 0.f);

    for (int d0 = 0; d0 < D_DIM; d0 += DSTAGE) {
        #pragma unroll
        for (int i = 0; i < 16; i++) {
            int idx = tid + 128 * i;
            int d = idx >> 5, x = idx & 31;
            *(float4*)&sW[d][4 * x] =
                *(const float4*)(Wt + (size_t)(d0 + d) * K_PAD + 4 * x);
        }
        #pragma unroll
        for (int i = 0; i < 2; i++) {
            int idx = tid + 128 * i;
            int b = idx >> 4, x = idx & 15;
            int bag = bag0 + b;
            float4 v = (bag < B_BAG)
                ? *(const float4*)(A + (size_t)bag * D_DIM + d0 + 4 * x)
                : make_float4(0.f, 0.f, 0.f, 0.f);
            sA[4 * x + 0][b] = v.x; sA[4 * x + 1][b] = v.y;
            sA[4 * x + 2][b] = v.z; sA[4 * x + 3][b] = v.w;
        }
        __syncthreads();

        #pragma unroll 16
        for (int d = 0; d < DSTAGE; d++) {
            float4 wv = *(const float4*)&sW[d][4 * kt];
            float4 av = *(const float4*)&sA[d][4 * bt];
            acc[0].x += av.x * wv.x; acc[0].y += av.x * wv.y;
            acc[0].z += av.x * wv.z; acc[0].w += av.x * wv.w;
            acc[1].x += av.y * wv.x; acc[1].y += av.y * wv.y;
            acc[1].z += av.y * wv.z; acc[1].w += av.y * wv.w;
            acc[2].x += av.z * wv.x; acc[2].y += av.z * wv.y;
            acc[2].z += av.z * wv.z; acc[2].w += av.z * wv.w;
            acc[3].x += av.w * wv.x; acc[3].y += av.w * wv.y;
            acc[3].z += av.w * wv.z; acc[3].w += av.w * wv.w;
        }
        __syncthreads();
    }

    #pragma unroll
    for (int r = 0; r < 4; r++) {
        int bag = bag0 + 4 * bt + r;
        if (bag >= B_BAG) continue;
        int k = 4 * kt;
        if (k + 4 <= K_TYP) {
            *(float4*)(out + (size_t)bag * K_TYP + k) = acc[r];
        } else if (k < K_TYP) {
            float v[4] = {acc[r].x, acc[r].y, acc[r].z, acc[r].w};
            for (int j = 0; j < 4 && k + j < K_TYP; j++)
                out[(size_t)bag * K_TYP + k + j] = v[j];
        }
    }
}

// ---------------------------------------------------------------------------
extern "C" void kernel_launch(void* const* d_in, const int* in_sizes, int n_in,
                              void* d_out, int out_size) {
    const int*   feature_seq    = (const int*)  d_in[0];
    const int*   offset_seq     = (const int*)  d_in[1];
    const int*   scope          = (const int*)  d_in[2];
    const float* typeTensor     = (const float*)d_in[3];
    const float* word_embedding = (const float*)d_in[4];
    const float* linear_weight  = (const float*)d_in[5];
    float*       out            = (float*)d_out;

    int*    mtype = nullptr;
    float  *bagE = nullptr, *Wt = nullptr;
    __half* embh = nullptr;
    cudaGetSymbolAddress((void**)&mtype, g_men_type);
    cudaGetSymbolAddress((void**)&bagE,  g_bag_emb);
    cudaGetSymbolAddress((void**)&Wt,    g_Wt);
    cudaGetSymbolAddress((void**)&embh,  g_emb_h);

    kc_conv<<<(V_VOC * D_DIM / 4 + 255) / 256, 256>>>(word_embedding, embh);
    k0_prep<<<K0_ARG_BLOCKS + K0_TR_BLOCKS, 256>>>(typeTensor, scope,
                                                   linear_weight, mtype, Wt);
    k1_mention<<<(2 * M_MEN) / 8, 256>>>(feature_seq, offset_seq,
                                         linear_weight, mtype);
    k3a_bagemb<<<B_BAG, 128>>>(scope, bagE);
    k3b_gemm<<<(B_BAG + GEMM_BM - 1) / GEMM_BM, 128>>>(bagE, Wt, out);
}

// round 10
// speedup vs baseline: 1.0074x; 1.0074x over previous
#include <cuda_runtime.h>
#include <cuda_fp16.h>

#define T_TOK 500000
#define M_MEN 50000
#define B_BAG 5000
#define V_VOC 100000
#define D_DIM 256
#define K_TYP 100
#define K_PAD 128

// Scratch (no allocations allowed)
__device__ __half g_emb_h[V_VOC * D_DIM];       // 51.2 MB fp16 embedding table
__device__ __half g_men_emb[M_MEN * D_DIM];     // 25.6 MB fp16 intermediate
__device__ float  g_sel_part[2 * M_MEN];        // per-half partial dots (fp32)
__device__ float  g_att[M_MEN];
__device__ float  g_bag_emb[B_BAG * D_DIM];     // 5.12 MB
__device__ float  g_Wt[D_DIM * K_PAD];          // 128 KB, W transposed d-major
__device__ int    g_men_type[M_MEN];            // per-mention selected type

#define CONV_N4      (V_VOC * D_DIM / 4)                 // 6.4M float4
#define CONV_BLOCKS  ((CONV_N4 + 255) / 256)             // 25000
#define ARG_BLOCKS   ((B_BAG + 7) / 8)                   // 625
#define TR_BLOCKS    ((D_DIM * K_PAD + 255) / 256)       // 128
#define PREP_BLOCKS  (CONV_BLOCKS + ARG_BLOCKS + TR_BLOCKS)

// ---------------------------------------------------------------------------
// K_prep (merged, one launch):
//   [0, CONV_BLOCKS)            : fp32 -> fp16 embedding table conversion
//   [CONV, CONV+ARG)            : per-bag argmax + mention-type scatter
//   [CONV+ARG, CONV+ARG+TR)     : W transpose -> Wt (d-major, k-padded)
// ---------------------------------------------------------------------------
__global__ void k_prep(const float* __restrict__ emb,
                       const float* __restrict__ typeT,
                       const int*   __restrict__ scope,
                       const float* __restrict__ W,
                       __half* __restrict__ emb_h,
                       int*    __restrict__ men_type,
                       float*  __restrict__ Wt) {
    unsigned bid = blockIdx.x;
    if (bid < CONV_BLOCKS) {
        int idx = bid * 256 + threadIdx.x;
        if (idx < CONV_N4) {
            float4 v = __ldcs(&((const float4*)emb)[idx]);  // stream fp32 copy
            __half2 h01 = __floats2half2_rn(v.x, v.y);
            __half2 h23 = __floats2half2_rn(v.z, v.w);
            uint2 packed;
            packed.x = *(const unsigned int*)&h01;
            packed.y = *(const unsigned int*)&h23;
            ((uint2*)emb_h)[idx] = packed;                  // fp16 table -> L2
        }
        return;
    }
    bid -= CONV_BLOCKS;
    if (bid >= ARG_BLOCKS) {
        int idx = (bid - ARG_BLOCKS) * 256 + threadIdx.x;
        if (idx < D_DIM * K_PAD) {
            int d = idx >> 7, k = idx & 127;
            Wt[idx] = (k < K_TYP) ? W[(size_t)k * D_DIM + d] : 0.f;
        }
        return;
    }
    int b    = bid * 8 + (threadIdx.x >> 5);
    int lane = threadIdx.x & 31;
    if (b >= B_BAG) return;
    float best = -INFINITY; int bi = K_TYP;
    for (int k = lane; k < K_TYP; k += 32) {
        float v = typeT[(size_t)b * K_TYP + k];
        if (v > best) { best = v; bi = k; }
    }
    #pragma unroll
    for (int off = 16; off; off >>= 1) {
        float ov = __shfl_xor_sync(0xffffffffu, best, off);
        int   oi = __shfl_xor_sync(0xffffffffu, bi,   off);
        if (ov > best || (ov == best && oi < bi)) { best = ov; bi = oi; }
    }
    int s = scope[b], e = scope[b + 1];
    for (int j = s + lane; j < e; j += 32) men_type[j] = bi;
}

// ---------------------------------------------------------------------------
// K1: TWO warps per mention (each owns 128 dims = 1 uint2 / 4 halves per lane).
//     Gathers from fp16 table (L2-resident), 4-token unroll, fp32 accumulate.
//     men_emb stored fp16 with PLAIN store (stays L2-resident for k3a).
// ---------------------------------------------------------------------------
__global__ void k1_mention(const int*   __restrict__ feat,
                           const int*   __restrict__ offs,
                           const float* __restrict__ lw,
                           const int*   __restrict__ men_type) {
    int wid  = threadIdx.x >> 5;               // 0..7
    int lane = threadIdx.x & 31;
    int gw   = blockIdx.x * 8 + wid;
    int m    = gw >> 1;
    int half = gw & 1;

    int start = offs[m];
    int end   = (m + 1 < M_MEN) ? offs[m + 1] : T_TOK;

    int col4 = half * 32 + lane;               // 4-dim group index (0..63)
    const uint2* eh = (const uint2*)g_emb_h;   // row = 64 uint2

    float4 acc = make_float4(0.f, 0.f, 0.f, 0.f);
    int p = start;
    for (; p + 4 <= end; p += 4) {
        int t0 = feat[p],     t1 = feat[p + 1];
        int t2 = feat[p + 2], t3 = feat[p + 3];
        uint2 u0 = eh[(size_t)t0 * 64 + col4];
        uint2 u1 = eh[(size_t)t1 * 64 + col4];
        uint2 u2 = eh[(size_t)t2 * 64 + col4];
        uint2 u3 = eh[(size_t)t3 * 64 + col4];
        float2 a0 = __half22float2(*(const __half2*)&u0.x);
        float2 b0 = __half22float2(*(const __half2*)&u0.y);
        float2 a1 = __half22float2(*(const __half2*)&u1.x);
        float2 b1 = __half22float2(*(const __half2*)&u1.y);
        float2 a2 = __half22float2(*(const __half2*)&u2.x);
        float2 b2 = __half22float2(*(const __half2*)&u2.y);
        float2 a3 = __half22float2(*(const __half2*)&u3.x);
        float2 b3 = __half22float2(*(const __half2*)&u3.y);
        acc.x += (a0.x + a1.x) + (a2.x + a3.x);
        acc.y += (a0.y + a1.y) + (a2.y + a3.y);
        acc.z += (b0.x + b1.x) + (b2.x + b3.x);
        acc.w += (b0.y + b1.y) + (b2.y + b3.y);
    }
    for (; p < end; p++) {
        int t0 = feat[p];
        uint2 u0 = eh[(size_t)t0 * 64 + col4];
        float2 a0 = __half22float2(*(const __half2*)&u0.x);
        float2 b0 = __half22float2(*(const __half2*)&u0.y);
        acc.x += a0.x; acc.y += a0.y; acc.z += b0.x; acc.w += b0.y;
    }
    float inv = 1.0f / (float)(end - start);
    acc.x *= inv; acc.y *= inv; acc.z *= inv; acc.w *= inv;

    // fp16 pack, plain store (L2-resident; read by k3a)
    __half2 h01 = __floats2half2_rn(acc.x, acc.y);
    __half2 h23 = __floats2half2_rn(acc.z, acc.w);
    uint2 packed;
    packed.x = *(const unsigned int*)&h01;
    packed.y = *(const unsigned int*)&h23;
    ((uint2*)g_men_emb)[(size_t)m * 64 + col4] = packed;

    int t = men_type[m];
    float4 w = ((const float4*)(lw + (size_t)t * D_DIM))[col4];
    float d = acc.x * w.x + acc.y * w.y + acc.z * w.z + acc.w * w.w;
    #pragma unroll
    for (int off = 16; off; off >>= 1) d += __shfl_xor_sync(0xffffffffu, d, off);
    if (lane == 0) g_sel_part[gw] = d;
}

// ---------------------------------------------------------------------------
// K2: warp per bag — softmax over sel (= part[2m]+part[2m+1]) -> att
// ---------------------------------------------------------------------------
__global__ void k2_att(const int* __restrict__ scope) {
    int b    = blockIdx.x * (blockDim.x >> 5) + (threadIdx.x >> 5);
    int lane = threadIdx.x & 31;
    if (b >= B_BAG) return;
    int s = scope[b], e = scope[b + 1];

    float mx = -INFINITY;
    for (int m = s + lane; m < e; m += 32)
        mx = fmaxf(mx, g_sel_part[2 * m] + g_sel_part[2 * m + 1]);
    #pragma unroll
    for (int off = 16; off; off >>= 1)
        mx = fmaxf(mx, __shfl_xor_sync(0xffffffffu, mx, off));

    float sum = 0.f;
    for (int m = s + lane; m < e; m += 32)
        sum += expf(g_sel_part[2 * m] + g_sel_part[2 * m + 1] - mx);
    #pragma unroll
    for (int off = 16; off; off >>= 1)
        sum += __shfl_xor_sync(0xffffffffu, sum, off);
    float inv = 1.0f / sum;

    for (int m = s + lane; m < e; m += 32)
        g_att[m] = expf(g_sel_part[2 * m] + g_sel_part[2 * m + 1] - mx) * inv;
}

// ---------------------------------------------------------------------------
// K3a: one 128-thread block per bag, lean (no softmax prologue, no syncs in
//      main loop). Thread (q=tid>>6, c=tid&63) accumulates fp16 column group
//      over mentions m = s+q, s+q+2, ...; 4 loads in flight (L2 hits expected).
// ---------------------------------------------------------------------------
__global__ void k3a_bagemb(const int* __restrict__ scope,
                           float*     __restrict__ bag_emb) {
    int b   = blockIdx.x;
    int tid = threadIdx.x;       // 128
    int q   = tid >> 6;          // 0..1 mention phase
    int c   = tid & 63;          // uint2 (4-half) column group
    int s = scope[b], e = scope[b + 1];

    const uint2* me = (const uint2*)g_men_emb;

    float4 acc = make_float4(0.f, 0.f, 0.f, 0.f);
    int m = s + q;
    for (; m + 6 < e; m += 8) {
        float w0 = __ldg(&g_att[m]);
        float w1 = __ldg(&g_att[m + 2]);
        float w2 = __ldg(&g_att[m + 4]);
        float w3 = __ldg(&g_att[m + 6]);
        uint2 u0 = __ldcg(&me[(size_t)m       * 64 + c]);
        uint2 u1 = __ldcg(&me[(size_t)(m + 2) * 64 + c]);
        uint2 u2 = __ldcg(&me[(size_t)(m + 4) * 64 + c]);
        uint2 u3 = __ldcg(&me[(size_t)(m + 6) * 64 + c]);
        float2 p0 = __half22float2(*(const __half2*)&u0.x);
        float2 q0 = __half22float2(*(const __half2*)&u0.y);
        float2 p1 = __half22float2(*(const __half2*)&u1.x);
        float2 q1 = __half22float2(*(const __half2*)&u1.y);
        float2 p2 = __half22float2(*(const __half2*)&u2.x);
        float2 q2 = __half22float2(*(const __half2*)&u2.y);
        float2 p3 = __half22float2(*(const __half2*)&u3.x);
        float2 q3 = __half22float2(*(const __half2*)&u3.y);
        acc.x += (w0 * p0.x + w1 * p1.x) + (w2 * p2.x + w3 * p3.x);
        acc.y += (w0 * p0.y + w1 * p1.y) + (w2 * p2.y + w3 * p3.y);
        acc.z += (w0 * q0.x + w1 * q1.x) + (w2 * q2.x + w3 * q3.x);
        acc.w += (w0 * q0.y + w1 * q1.y) + (w2 * q2.y + w3 * q3.y);
    }
    for (; m < e; m += 2) {
        float w0 = __ldg(&g_att[m]);
        uint2 u0 = __ldcg(&me[(size_t)m * 64 + c]);
        float2 p0 = __half22float2(*(const __half2*)&u0.x);
        float2 q0 = __half22float2(*(const __half2*)&u0.y);
        acc.x += w0 * p0.x; acc.y += w0 * p0.y;
        acc.z += w0 * q0.x; acc.w += w0 * q0.y;
    }

    __shared__ float4 red[2][64];
    red[q][c] = acc;
    __syncthreads();
    if (tid < 64) {
        float4 r0 = red[0][tid], r1 = red[1][tid];
        float4 r;
        r.x = r0.x + r1.x; r.y = r0.y + r1.y;
        r.z = r0.z + r1.z; r.w = r0.w + r1.w;
        ((float4*)(bag_emb + (size_t)b * D_DIM))[tid] = r;
    }
}

// ---------------------------------------------------------------------------
// K3b: GEMM out[5000,100] = bag_emb @ W^T using d-major g_Wt.
// ---------------------------------------------------------------------------
#define GEMM_BM 16
#define DSTAGE  64
__global__ void k3b_gemm(const float* __restrict__ A,
                         const float* __restrict__ Wt,
                         float*       __restrict__ out) {
    __shared__ float sW[DSTAGE][K_PAD];
    __shared__ float sA[DSTAGE][GEMM_BM + 4];
    int tid = threadIdx.x;                    // 128 threads
    int kt = tid & 31;
    int bt = tid >> 5;
    int bag0 = blockIdx.x * GEMM_BM;

    float4 acc[4];
    #pragma unroll
    for (int r = 0; r < 4; r++) acc[r] = make_float4(0.f, 0.f, 0.f, 0.f);

    for (int d0 = 0; d0 < D_DIM; d0 += DSTAGE) {
        #pragma unroll
        for (int i = 0; i < 16; i++) {
            int idx = tid + 128 * i;
            int d = idx >> 5, x = idx & 31;
            *(float4*)&sW[d][4 * x] =
                *(const float4*)(Wt + (size_t)(d0 + d) * K_PAD + 4 * x);
        }
        #pragma unroll
        for (int i = 0; i < 2; i++) {
            int idx = tid + 128 * i;
            int b = idx >> 4, x = idx & 15;
            int bag = bag0 + b;
            float4 v = (bag < B_BAG)
                ? *(const float4*)(A + (size_t)bag * D_DIM + d0 + 4 * x)
                : make_float4(0.f, 0.f, 0.f, 0.f);
            sA[4 * x + 0][b] = v.x; sA[4 * x + 1][b] = v.y;
            sA[4 * x + 2][b] = v.z; sA[4 * x + 3][b] = v.w;
        }
        __syncthreads();

        #pragma unroll 16
        for (int d = 0; d < DSTAGE; d++) {
            float4 wv = *(const float4*)&sW[d][4 * kt];
            float4 av = *(const float4*)&sA[d][4 * bt];
            acc[0].x += av.x * wv.x; acc[0].y += av.x * wv.y;
            acc[0].z += av.x * wv.z; acc[0].w += av.x * wv.w;
            acc[1].x += av.y * wv.x; acc[1].y += av.y * wv.y;
            acc[1].z += av.y * wv.z; acc[1].w += av.y * wv.w;
            acc[2].x += av.z * wv.x; acc[2].y += av.z * wv.y;
            acc[2].z += av.z * wv.z; acc[2].w += av.z * wv.w;
            acc[3].x += av.w * wv.x; acc[3].y += av.w * wv.y;
            acc[3].z += av.w * wv.z; acc[3].w += av.w * wv.w;
        }
        __syncthreads();
    }

    #pragma unroll
    for (int r = 0; r < 4; r++) {
        int bag = bag0 + 4 * bt + r;
        if (bag >= B_BAG) continue;
        int k = 4 * kt;
        if (k + 4 <= K_TYP) {
            *(float4*)(out + (size_t)bag * K_TYP + k) = acc[r];
        } else if (k < K_TYP) {
            float v[4] = {acc[r].x, acc[r].y, acc[r].z, acc[r].w};
            for (int j = 0; j < 4 && k + j < K_TYP; j++)
                out[(size_t)bag * K_TYP + k + j] = v[j];
        }
    }
}

// ---------------------------------------------------------------------------
extern "C" void kernel_launch(void* const* d_in, const int* in_sizes, int n_in,
                              void* d_out, int out_size) {
    const int*   feature_seq    = (const int*)  d_in[0];
    const int*   offset_seq     = (const int*)  d_in[1];
    const int*   scope          = (const int*)  d_in[2];
    const float* typeTensor     = (const float*)d_in[3];
    const float* word_embedding = (const float*)d_in[4];
    const float* linear_weight  = (const float*)d_in[5];
    float*       out            = (float*)d_out;

    int*    mtype = nullptr;
    float  *bagE = nullptr, *Wt = nullptr;
    __half* embh = nullptr;
    cudaGetSymbolAddress((void**)&mtype, g_men_type);
    cudaGetSymbolAddress((void**)&bagE,  g_bag_emb);
    cudaGetSymbolAddress((void**)&Wt,    g_Wt);
    cudaGetSymbolAddress((void**)&embh,  g_emb_h);

    k_prep<<<PREP_BLOCKS, 256>>>(word_embedding, typeTensor, scope,
                                 linear_weight, embh, mtype, Wt);
    k1_mention<<<(2 * M_MEN) / 8, 256>>>(feature_seq, offset_seq,
                                         linear_weight, mtype);
    k2_att<<<(B_BAG + 7) / 8, 256>>>(scope);
    k3a_bagemb<<<B_BAG, 128>>>(scope, bagE);
    k3b_gemm<<<(B_BAG + GEMM_BM - 1) / GEMM_BM, 128>>>(bagE, Wt, out);
}